// round 1
// baseline (speedup 1.0000x reference)
#include <cuda_runtime.h>
#include <cstddef>

// Problem constants
#define BATCH 4
#define SEQ   2048
#define EMB   512
#define HEADS 8
#define KDIM  64
#define TOKENS (BATCH * SEQ)          // 8192

// Scratch (allocation-free rule: __device__ globals)
__device__ float g_q  [TOKENS * EMB];   // Q = x @ Wq, [tok, h*64+d]
__device__ float g_ctx[TOKENS * EMB];   // context,    [tok, h*64+d]

// ---------------------------------------------------------------------------
// SGEMM: C[M,N] = A[M,K] @ B[K,N], fp32. 64x64 tile, BK=16, 256 thr, 4x4 micro
// ---------------------------------------------------------------------------
__global__ __launch_bounds__(256) void sgemm64(
    const float* __restrict__ A, const float* __restrict__ Bm,
    float* __restrict__ C, int M, int N, int K)
{
    __shared__ float As[16][64];   // As[k][m] (A tile transposed)
    __shared__ float Bs[16][64];   // Bs[k][n]

    const int tid = threadIdx.x;
    const int tx = tid & 15, ty = tid >> 4;
    const int bn = blockIdx.x << 6;
    const int bm = blockIdx.y << 6;

    float acc[4][4];
#pragma unroll
    for (int i = 0; i < 4; ++i)
#pragma unroll
        for (int j = 0; j < 4; ++j) acc[i][j] = 0.f;

    for (int kt = 0; kt < K; kt += 16) {
        {   // A tile: 64 rows x 16 k -> 256 float4
            const int m  = tid >> 2;
            const int k4 = (tid & 3) << 2;
            float4 a = *(const float4*)&A[(size_t)(bm + m) * K + kt + k4];
            As[k4 + 0][m] = a.x; As[k4 + 1][m] = a.y;
            As[k4 + 2][m] = a.z; As[k4 + 3][m] = a.w;
            // B tile: 16 k x 64 n
            const int k  = tid >> 4;
            const int n4 = (tid & 15) << 2;
            *(float4*)&Bs[k][n4] = *(const float4*)&Bm[(size_t)(kt + k) * N + bn + n4];
        }
        __syncthreads();
#pragma unroll
        for (int k = 0; k < 16; ++k) {
            float4 a4 = *(const float4*)&As[k][ty << 2];
            float4 b4 = *(const float4*)&Bs[k][tx << 2];
            float av[4] = {a4.x, a4.y, a4.z, a4.w};
            float bv[4] = {b4.x, b4.y, b4.z, b4.w};
#pragma unroll
            for (int i = 0; i < 4; ++i)
#pragma unroll
                for (int j = 0; j < 4; ++j) acc[i][j] += av[i] * bv[j];
        }
        __syncthreads();
    }
#pragma unroll
    for (int i = 0; i < 4; ++i) {
        float4 r = make_float4(acc[i][0], acc[i][1], acc[i][2], acc[i][3]);
        *(float4*)&C[(size_t)(bm + (ty << 2) + i) * N + bn + (tx << 2)] = r;
    }
}

// ---------------------------------------------------------------------------
// Flash attention (fp32): one CTA per (b,h, 64-query tile).
// Streams K/V in 64-row tiles, online softmax, PV accumulated in registers.
// ---------------------------------------------------------------------------
__global__ __launch_bounds__(256) void attn64(
    const float* __restrict__ Q,   // [tok, 512] from g_q
    const float* __restrict__ Kg,  // [B,H,S,64]
    const float* __restrict__ Vg,  // [B,H,S,64]
    float* __restrict__ Ctx)       // [tok, 512]
{
    __shared__ float Qst[64][64];  // Qst[d][r]  (transposed, pre-scaled)
    __shared__ float KPt[64][64];  // K^T then P^T (reused)
    __shared__ float Vs [64][64];  // Vs[c][d]

    const int tid = threadIdx.x;
    const int tx = tid & 15, ty = tid >> 4;
    const int bh = blockIdx.y;            // 0..31
    const int b  = bh >> 3, h = bh & 7;
    const int q0 = blockIdx.x << 6;

    // Load Q tile, transpose, scale by 1/sqrt(64)
#pragma unroll
    for (int it = 0; it < 4; ++it) {
        int v = tid + (it << 8);
        int r = v >> 4, d = (v & 15) << 2;
        float4 qv = *(const float4*)&Q[(size_t)(b * SEQ + q0 + r) * EMB + h * KDIM + d];
        Qst[d + 0][r] = qv.x * 0.125f;
        Qst[d + 1][r] = qv.y * 0.125f;
        Qst[d + 2][r] = qv.z * 0.125f;
        Qst[d + 3][r] = qv.w * 0.125f;
    }

    float m[4], l[4], o[4][4];
#pragma unroll
    for (int i = 0; i < 4; ++i) {
        m[i] = -1e30f; l[i] = 0.f;
#pragma unroll
        for (int j = 0; j < 4; ++j) o[i][j] = 0.f;
    }

    const float* kb = Kg + (size_t)bh * (SEQ * KDIM);
    const float* vb = Vg + (size_t)bh * (SEQ * KDIM);

    for (int kt = 0; kt < SEQ / 64; ++kt) {
        __syncthreads();   // previous iteration's smem reads done
        // Load K (transposed) and V (natural)
#pragma unroll
        for (int it = 0; it < 4; ++it) {
            int v = tid + (it << 8);
            int r = v >> 4, d = (v & 15) << 2;
            float4 kv = *(const float4*)&kb[(size_t)((kt << 6) + r) * KDIM + d];
            KPt[d + 0][r] = kv.x; KPt[d + 1][r] = kv.y;
            KPt[d + 2][r] = kv.z; KPt[d + 3][r] = kv.w;
            *(float4*)&Vs[r][d] = *(const float4*)&vb[(size_t)((kt << 6) + r) * KDIM + d];
        }
        __syncthreads();

        // S = Q K^T  (rows r0=4*ty, cols c0=4*tx)
        float s[4][4];
#pragma unroll
        for (int i = 0; i < 4; ++i)
#pragma unroll
            for (int j = 0; j < 4; ++j) s[i][j] = 0.f;
#pragma unroll 8
        for (int d = 0; d < 64; ++d) {
            float4 a4 = *(const float4*)&Qst[d][ty << 2];
            float4 c4 = *(const float4*)&KPt[d][tx << 2];
            float av[4] = {a4.x, a4.y, a4.z, a4.w};
            float cv[4] = {c4.x, c4.y, c4.z, c4.w};
#pragma unroll
            for (int i = 0; i < 4; ++i)
#pragma unroll
                for (int j = 0; j < 4; ++j) s[i][j] += av[i] * cv[j];
        }

        // Online softmax per row (row stats replicated over the 16 tx lanes)
#pragma unroll
        for (int i = 0; i < 4; ++i) {
            float tm = fmaxf(fmaxf(s[i][0], s[i][1]), fmaxf(s[i][2], s[i][3]));
            tm = fmaxf(tm, __shfl_xor_sync(0xffffffffu, tm, 1, 16));
            tm = fmaxf(tm, __shfl_xor_sync(0xffffffffu, tm, 2, 16));
            tm = fmaxf(tm, __shfl_xor_sync(0xffffffffu, tm, 4, 16));
            tm = fmaxf(tm, __shfl_xor_sync(0xffffffffu, tm, 8, 16));
            float mn    = fmaxf(m[i], tm);
            float scale = __expf(m[i] - mn);
            m[i] = mn;
            float ps = 0.f;
#pragma unroll
            for (int j = 0; j < 4; ++j) { s[i][j] = __expf(s[i][j] - mn); ps += s[i][j]; }
            ps += __shfl_xor_sync(0xffffffffu, ps, 1, 16);
            ps += __shfl_xor_sync(0xffffffffu, ps, 2, 16);
            ps += __shfl_xor_sync(0xffffffffu, ps, 4, 16);
            ps += __shfl_xor_sync(0xffffffffu, ps, 8, 16);
            l[i] = l[i] * scale + ps;
#pragma unroll
            for (int j = 0; j < 4; ++j) o[i][j] *= scale;
        }

        __syncthreads();   // all S reads of KPt done before overwrite with P^T
#pragma unroll
        for (int i = 0; i < 4; ++i)
#pragma unroll
            for (int j = 0; j < 4; ++j)
                KPt[(tx << 2) + j][(ty << 2) + i] = s[i][j];
        __syncthreads();

        // O += P V   (rows r0=4*ty, dims d0=4*tx)
#pragma unroll 8
        for (int c = 0; c < 64; ++c) {
            float4 p4 = *(const float4*)&KPt[c][ty << 2];
            float4 v4 = *(const float4*)&Vs[c][tx << 2];
            float pv[4] = {p4.x, p4.y, p4.z, p4.w};
            float vv[4] = {v4.x, v4.y, v4.z, v4.w};
#pragma unroll
            for (int i = 0; i < 4; ++i)
#pragma unroll
                for (int j = 0; j < 4; ++j) o[i][j] += pv[i] * vv[j];
        }
    }

    // Normalize and write ctx [tok, h*64+d]
#pragma unroll
    for (int i = 0; i < 4; ++i) {
        float inv = 1.f / l[i];
        float4 r = make_float4(o[i][0] * inv, o[i][1] * inv, o[i][2] * inv, o[i][3] * inv);
        *(float4*)&Ctx[(size_t)(b * SEQ + q0 + (ty << 2) + i) * EMB + h * KDIM + (tx << 2)] = r;
    }
}

// ---------------------------------------------------------------------------
extern "C" void kernel_launch(void* const* d_in, const int* in_sizes, int n_in,
                              void* d_out, int out_size)
{
    const float* x   = (const float*)d_in[0];   // [4,2048,512]
    const float* key = (const float*)d_in[1];   // [4,8,2048,64]
    const float* val = (const float*)d_in[2];   // [4,8,2048,64]
    const float* wq  = (const float*)d_in[3];   // [512,512]
    const float* wo  = (const float*)d_in[4];   // [512,512]
    float* out = (float*)d_out;                 // [4,2048,512]

    float *qptr, *cptr;
    cudaGetSymbolAddress((void**)&qptr, g_q);
    cudaGetSymbolAddress((void**)&cptr, g_ctx);

    // 1) Q = x @ Wq   : [8192,512] x [512,512]
    sgemm64<<<dim3(EMB / 64, TOKENS / 64), 256>>>(x, wq, qptr, TOKENS, EMB, EMB);
    // 2) attention    : grid (q-tiles, b*h)
    attn64<<<dim3(SEQ / 64, BATCH * HEADS), 256>>>(qptr, key, val, cptr);
    // 3) out = ctx @ Wo
    sgemm64<<<dim3(EMB / 64, TOKENS / 64), 256>>>(cptr, wo, out, TOKENS, EMB, EMB);
}

// round 2
// speedup vs baseline: 1.4796x; 1.4796x over previous
#include <cuda_runtime.h>
#include <cstddef>

// Problem constants
#define BATCH 4
#define SEQ   2048
#define EMB   512
#define HEADS 8
#define KDIM  64
#define TOKENS (BATCH * SEQ)          // 8192

// Scratch (allocation-free rule: __device__ globals)
__device__ float g_q  [TOKENS * EMB];   // Q = x @ Wq, [tok, h*64+d]
__device__ float g_ctx[TOKENS * EMB];   // context,    [tok, h*64+d]

// ---------------------------------------------------------------------------
// helpers
// ---------------------------------------------------------------------------
__device__ __forceinline__ float tf32r(float x) {
    float y;
    asm("cvt.rna.tf32.f32 %0, %1;" : "=f"(y) : "f"(x));
    return y;
}

__device__ __forceinline__ void mma_tf32(float* c,
                                         float a0, float a1, float a2, float a3,
                                         float b0, float b1)
{
    asm volatile(
        "mma.sync.aligned.m16n8k8.row.col.f32.tf32.tf32.f32 "
        "{%0,%1,%2,%3}, {%4,%5,%6,%7}, {%8,%9}, {%0,%1,%2,%3};\n"
        : "+f"(c[0]), "+f"(c[1]), "+f"(c[2]), "+f"(c[3])
        : "r"(__float_as_uint(a0)), "r"(__float_as_uint(a1)),
          "r"(__float_as_uint(a2)), "r"(__float_as_uint(a3)),
          "r"(__float_as_uint(b0)), "r"(__float_as_uint(b1)));
}

// ---------------------------------------------------------------------------
// SGEMM: C[M,N] = A[M,K] @ B[K,N], fp32. 64x64 tile, BK=16, 256 thr, 4x4 micro
// (used for the two projection GEMMs; needs fp32 precision for the logits)
// ---------------------------------------------------------------------------
__global__ __launch_bounds__(256) void sgemm64(
    const float* __restrict__ A, const float* __restrict__ Bm,
    float* __restrict__ C, int M, int N, int K)
{
    __shared__ float As[16][64];   // As[k][m] (A tile transposed)
    __shared__ float Bs[16][64];   // Bs[k][n]

    const int tid = threadIdx.x;
    const int tx = tid & 15, ty = tid >> 4;
    const int bn = blockIdx.x << 6;
    const int bm = blockIdx.y << 6;

    float acc[4][4];
#pragma unroll
    for (int i = 0; i < 4; ++i)
#pragma unroll
        for (int j = 0; j < 4; ++j) acc[i][j] = 0.f;

    for (int kt = 0; kt < K; kt += 16) {
        {
            const int m  = tid >> 2;
            const int k4 = (tid & 3) << 2;
            float4 a = *(const float4*)&A[(size_t)(bm + m) * K + kt + k4];
            As[k4 + 0][m] = a.x; As[k4 + 1][m] = a.y;
            As[k4 + 2][m] = a.z; As[k4 + 3][m] = a.w;
            const int k  = tid >> 4;
            const int n4 = (tid & 15) << 2;
            *(float4*)&Bs[k][n4] = *(const float4*)&Bm[(size_t)(kt + k) * N + bn + n4];
        }
        __syncthreads();
#pragma unroll
        for (int k = 0; k < 16; ++k) {
            float4 a4 = *(const float4*)&As[k][ty << 2];
            float4 b4 = *(const float4*)&Bs[k][tx << 2];
            float av[4] = {a4.x, a4.y, a4.z, a4.w};
            float bv[4] = {b4.x, b4.y, b4.z, b4.w};
#pragma unroll
            for (int i = 0; i < 4; ++i)
#pragma unroll
                for (int j = 0; j < 4; ++j) acc[i][j] += av[i] * bv[j];
        }
        __syncthreads();
    }
#pragma unroll
    for (int i = 0; i < 4; ++i) {
        float4 r = make_float4(acc[i][0], acc[i][1], acc[i][2], acc[i][3]);
        *(float4*)&C[(size_t)(bm + (ty << 2) + i) * N + bn + (tx << 2)] = r;
    }
}

// ---------------------------------------------------------------------------
// Flash attention on tensor cores (tf32 3-way split => ~fp32 accuracy).
// 1 CTA = 256 thr = 8 warps, per (b, h, 128-query tile). Each warp owns 16
// query rows. K/V streamed in 64-row tiles. Q fragments live in registers.
// mma.sync.m16n8k8 fragment layouts (row.col):
//   A(16x8): a0=(g,t) a1=(g+8,t) a2=(g,t+4) a3=(g+8,t+4)   g=lane>>2, t=lane&3
//   B(8x8) : b0=(k=t, n=g) b1=(k=t+4, n=g)
//   C(16x8): c0=(g,2t) c1=(g,2t+1) c2=(g+8,2t) c3=(g+8,2t+1)
// ---------------------------------------------------------------------------
#define KPAD 68   // bank = 4*n + k  -> conflict-free for K-fragment loads
#define VPAD 72   // bank = 8*t + g  -> conflict-free for V-fragment loads

__global__ __launch_bounds__(256) void attn_mma(
    const float* __restrict__ Q,   // [tok, 512] from g_q
    const float* __restrict__ Kg,  // [B,H,S,64]
    const float* __restrict__ Vg,  // [B,H,S,64]
    float* __restrict__ Ctx)       // [tok, 512]
{
    __shared__ float Ks[64][KPAD];
    __shared__ float Vs[64][VPAD];

    const int tid  = threadIdx.x;
    const int warp = tid >> 5, lane = tid & 31;
    const int gq = lane >> 2, tq = lane & 3;
    const int bh = blockIdx.y;
    const int b  = bh >> 3, h = bh & 7;
    const int q0 = blockIdx.x << 7;           // 128-query tile
    const int row0 = q0 + warp * 16 + gq;     // query rows owned by this thread
    const int row1 = row0 + 8;

    // ---- Q fragments (hi/lo split), pre-scaled by 1/sqrt(64) ----
    float qh[8][4], ql[8][4];
    {
        const float* qp = Q + (size_t)(b * SEQ) * EMB + h * KDIM;
#pragma unroll
        for (int c = 0; c < 8; ++c) {
            float v[4];
            v[0] = qp[(size_t)row0 * EMB + c * 8 + tq]     * 0.125f;
            v[1] = qp[(size_t)row1 * EMB + c * 8 + tq]     * 0.125f;
            v[2] = qp[(size_t)row0 * EMB + c * 8 + tq + 4] * 0.125f;
            v[3] = qp[(size_t)row1 * EMB + c * 8 + tq + 4] * 0.125f;
#pragma unroll
            for (int i = 0; i < 4; ++i) {
                qh[c][i] = tf32r(v[i]);
                ql[c][i] = v[i] - qh[c][i];
            }
        }
    }

    float oacc[8][4];
#pragma unroll
    for (int n = 0; n < 8; ++n)
#pragma unroll
        for (int i = 0; i < 4; ++i) oacc[n][i] = 0.f;
    float m0 = -1e30f, m1 = -1e30f, l0 = 0.f, l1 = 0.f;

    const float* kb = Kg + (size_t)bh * SEQ * KDIM;
    const float* vb = Vg + (size_t)bh * SEQ * KDIM;

    for (int kt = 0; kt < SEQ / 64; ++kt) {
        __syncthreads();
#pragma unroll
        for (int it = 0; it < 4; ++it) {
            int idx = tid + (it << 8);
            int r = idx >> 4, c4 = (idx & 15) << 2;
            *(float4*)&Ks[r][c4] =
                *(const float4*)&kb[((size_t)(kt << 6) + r) * KDIM + c4];
            *(float4*)&Vs[r][c4] =
                *(const float4*)&vb[((size_t)(kt << 6) + r) * KDIM + c4];
        }
        __syncthreads();

        // ---- S = Q K^T (16x64 per warp), tf32 3x split ----
        float sacc[8][4];
#pragma unroll
        for (int n = 0; n < 8; ++n)
#pragma unroll
            for (int i = 0; i < 4; ++i) sacc[n][i] = 0.f;

#pragma unroll
        for (int kc = 0; kc < 8; ++kc) {
#pragma unroll
            for (int n = 0; n < 8; ++n) {
                float b0 = Ks[n * 8 + gq][kc * 8 + tq];
                float b1 = Ks[n * 8 + gq][kc * 8 + tq + 4];
                float bh0 = tf32r(b0), bl0 = b0 - bh0;
                float bh1 = tf32r(b1), bl1 = b1 - bh1;
                mma_tf32(sacc[n], qh[kc][0], qh[kc][1], qh[kc][2], qh[kc][3], bh0, bh1);
                mma_tf32(sacc[n], qh[kc][0], qh[kc][1], qh[kc][2], qh[kc][3], bl0, bl1);
                mma_tf32(sacc[n], ql[kc][0], ql[kc][1], ql[kc][2], ql[kc][3], bh0, bh1);
            }
        }

        // ---- online softmax (row0 via c0/c1, row1 via c2/c3; quad-reduce) ----
        float tm0 = -1e30f, tm1 = -1e30f;
#pragma unroll
        for (int n = 0; n < 8; ++n) {
            tm0 = fmaxf(tm0, fmaxf(sacc[n][0], sacc[n][1]));
            tm1 = fmaxf(tm1, fmaxf(sacc[n][2], sacc[n][3]));
        }
        tm0 = fmaxf(tm0, __shfl_xor_sync(0xffffffffu, tm0, 1));
        tm0 = fmaxf(tm0, __shfl_xor_sync(0xffffffffu, tm0, 2));
        tm1 = fmaxf(tm1, __shfl_xor_sync(0xffffffffu, tm1, 1));
        tm1 = fmaxf(tm1, __shfl_xor_sync(0xffffffffu, tm1, 2));
        float n0 = fmaxf(m0, tm0), n1 = fmaxf(m1, tm1);
        float sc0 = __expf(m0 - n0), sc1 = __expf(m1 - n1);
        m0 = n0; m1 = n1;
        float ps0 = 0.f, ps1 = 0.f;
#pragma unroll
        for (int n = 0; n < 8; ++n) {
            sacc[n][0] = __expf(sacc[n][0] - n0); ps0 += sacc[n][0];
            sacc[n][1] = __expf(sacc[n][1] - n0); ps0 += sacc[n][1];
            sacc[n][2] = __expf(sacc[n][2] - n1); ps1 += sacc[n][2];
            sacc[n][3] = __expf(sacc[n][3] - n1); ps1 += sacc[n][3];
        }
        ps0 += __shfl_xor_sync(0xffffffffu, ps0, 1);
        ps0 += __shfl_xor_sync(0xffffffffu, ps0, 2);
        ps1 += __shfl_xor_sync(0xffffffffu, ps1, 1);
        ps1 += __shfl_xor_sync(0xffffffffu, ps1, 2);
        l0 = l0 * sc0 + ps0;
        l1 = l1 * sc1 + ps1;
#pragma unroll
        for (int n = 0; n < 8; ++n) {
            oacc[n][0] *= sc0; oacc[n][1] *= sc0;
            oacc[n][2] *= sc1; oacc[n][3] *= sc1;
        }

        // ---- O += P V : convert P accumulator frags -> A frags via shuffles ----
        const int srcA = (lane & ~3) | (tq >> 1);   // cols q   (q = tq)
        const int srcB = srcA + 2;                  // cols q+4
#pragma unroll
        for (int kc = 0; kc < 8; ++kc) {
            float v0 = __shfl_sync(0xffffffffu, sacc[kc][0], srcA);
            float v1 = __shfl_sync(0xffffffffu, sacc[kc][1], srcA);
            float v2 = __shfl_sync(0xffffffffu, sacc[kc][2], srcA);
            float v3 = __shfl_sync(0xffffffffu, sacc[kc][3], srcA);
            float w0 = __shfl_sync(0xffffffffu, sacc[kc][0], srcB);
            float w1 = __shfl_sync(0xffffffffu, sacc[kc][1], srcB);
            float w2 = __shfl_sync(0xffffffffu, sacc[kc][2], srcB);
            float w3 = __shfl_sync(0xffffffffu, sacc[kc][3], srcB);
            const bool odd = (tq & 1);
            float a0 = odd ? v1 : v0;   // P[row0][q]
            float a1 = odd ? v3 : v2;   // P[row1][q]
            float a2 = odd ? w1 : w0;   // P[row0][q+4]
            float a3 = odd ? w3 : w2;   // P[row1][q+4]
            float ah0 = tf32r(a0), al0 = a0 - ah0;
            float ah1 = tf32r(a1), al1 = a1 - ah1;
            float ah2 = tf32r(a2), al2 = a2 - ah2;
            float ah3 = tf32r(a3), al3 = a3 - ah3;
#pragma unroll
            for (int dt = 0; dt < 8; ++dt) {
                float b0 = Vs[kc * 8 + tq][dt * 8 + gq];
                float b1 = Vs[kc * 8 + tq + 4][dt * 8 + gq];
                float bh0 = tf32r(b0), bl0 = b0 - bh0;
                float bh1 = tf32r(b1), bl1 = b1 - bh1;
                mma_tf32(oacc[dt], ah0, ah1, ah2, ah3, bh0, bh1);
                mma_tf32(oacc[dt], al0, al1, al2, al3, bh0, bh1);
                mma_tf32(oacc[dt], ah0, ah1, ah2, ah3, bl0, bl1);
            }
        }
    }

    // ---- normalize + write ctx [tok, h*64+d] ----
    float inv0 = 1.f / l0, inv1 = 1.f / l1;
    float* cp = Ctx + (size_t)(b * SEQ) * EMB + h * KDIM;
#pragma unroll
    for (int dt = 0; dt < 8; ++dt) {
        *(float2*)&cp[(size_t)row0 * EMB + dt * 8 + 2 * tq] =
            make_float2(oacc[dt][0] * inv0, oacc[dt][1] * inv0);
        *(float2*)&cp[(size_t)row1 * EMB + dt * 8 + 2 * tq] =
            make_float2(oacc[dt][2] * inv1, oacc[dt][3] * inv1);
    }
}

// ---------------------------------------------------------------------------
extern "C" void kernel_launch(void* const* d_in, const int* in_sizes, int n_in,
                              void* d_out, int out_size)
{
    const float* x   = (const float*)d_in[0];   // [4,2048,512]
    const float* key = (const float*)d_in[1];   // [4,8,2048,64]
    const float* val = (const float*)d_in[2];   // [4,8,2048,64]
    const float* wq  = (const float*)d_in[3];   // [512,512]
    const float* wo  = (const float*)d_in[4];   // [512,512]
    float* out = (float*)d_out;                 // [4,2048,512]

    float *qptr, *cptr;
    cudaGetSymbolAddress((void**)&qptr, g_q);
    cudaGetSymbolAddress((void**)&cptr, g_ctx);

    // 1) Q = x @ Wq   : [8192,512] x [512,512]
    sgemm64<<<dim3(EMB / 64, TOKENS / 64), 256>>>(x, wq, qptr, TOKENS, EMB, EMB);
    // 2) attention    : grid (q-tiles of 128, b*h)
    attn_mma<<<dim3(SEQ / 128, BATCH * HEADS), 256>>>(qptr, key, val, cptr);
    // 3) out = ctx @ Wo
    sgemm64<<<dim3(EMB / 64, TOKENS / 64), 256>>>(cptr, wo, out, TOKENS, EMB, EMB);
}